// round 16
// baseline (speedup 1.0000x reference)
#include <cuda_runtime.h>
#include <cuda_fp16.h>
#include <cstdint>
#include <math.h>

#define Bb   8
#define Cc   256
#define Hh   64
#define Ww   64
#define HW   (Hh*Ww)
#define Nn   (Bb*HW)
#define KD   1024
#define OUT_ELEMS ((size_t)Bb*Cc*HW)

#define EPS_NORM 1e-12f
#define EPS_Z    1e-6f
#define RATE     0.999f

// ---------------- scratch ----------------------------------------------------
__device__ __half d_xfh [(size_t)Nn*Cc];
__device__ float  d_rinv[Nn];
__device__ float  d_g   [(size_t)Nn*Cc];
__device__ float  d_xo  [(size_t)Nn*Cc];
__device__ __half d_qcat[(size_t)Nn*2*Cc];
__device__ __half d_bigBh[(size_t)(Cc+KD)*Cc];
__device__ float  d_mnew[(size_t)KD*Cc];
__device__ float  d_kk  [(size_t)KD*2*Cc];
__device__ int    d_cnt [KD];
__device__ int    d_off [KD];
__device__ int    d_cur [KD];
__device__ int    d_rowlist[Nn];
__device__ unsigned long long d_best[Nn];
__device__ float  d_kmean[2*Cc];
__device__ __half d_BmatTh[(size_t)Cc*2*Cc];
__device__ float  d_z [Nn];
__device__ float  d_z2[Nn];

// ---------------- helpers -----------------------------------------------------
__device__ __forceinline__ void cp_async16(uint32_t smem_dst, const void* gsrc) {
    asm volatile("cp.async.cg.shared.global [%0], [%1], 16;" :: "r"(smem_dst), "l"(gsrc));
}
#define CP_COMMIT() asm volatile("cp.async.commit_group;" ::: "memory")
#define CP_WAIT(n)  asm volatile("cp.async.wait_group %0;" :: "n"(n) : "memory")

__device__ __forceinline__ void ldsm_x4(uint32_t& r0, uint32_t& r1, uint32_t& r2,
                                        uint32_t& r3, uint32_t a) {
    asm volatile("ldmatrix.sync.aligned.m8n8.x4.shared.b16 {%0,%1,%2,%3}, [%4];"
        : "=r"(r0), "=r"(r1), "=r"(r2), "=r"(r3) : "r"(a));
}
__device__ __forceinline__ void ldsm_x2(uint32_t& r0, uint32_t& r1, uint32_t a) {
    asm volatile("ldmatrix.sync.aligned.m8n8.x2.shared.b16 {%0,%1}, [%2];"
        : "=r"(r0), "=r"(r1) : "r"(a));
}

__device__ __forceinline__ float sigp(float pw) {
    return 1.0f + 4.0f / (1.0f + __expf(-pw));
}

__device__ __forceinline__ void pow_pair(float v, float p, float& qp, float& qn) {
    float e;
    if (p == 3.0f) {
        float a = fabsf(v);
        e = a*a*a;
    } else {
        e = exp2f(p * __log2f(fabsf(v)));
    }
    qp = (v > 0.f) ? e : 0.f;
    qn = (v < 0.f) ? e : 0.f;
}

// ---------------- fp16 mma.sync NT GEMM (2-stage cp.async, 3 CTAs/SM) -------
// MODE 0: score (*rinv, argmax)  MODE 1: g (+bias)  MODE 2: xo (*z/z2*escale)
#define KT       64
#define HSTRIDE  72
#define TEN_HALVES (128*HSTRIDE)
#define STG_HALVES (2*TEN_HALVES)
#define STG_BYTES  (STG_HALVES*2)            // 36864
#define TEN_BYTES  (TEN_HALVES*2)
#define MMA_SMEM_BYTES (2*STG_BYTES)         // 73728 -> 3 CTAs/SM

template<int MODE>
__global__ __launch_bounds__(256, 3)
void k_mma(const __half* __restrict__ A, const __half* __restrict__ B,
           float* __restrict__ C1, const float* __restrict__ bias,
           int Kd, float escale)
{
    extern __shared__ __half sh[];
    const uint32_t shBase = (uint32_t)__cvta_generic_to_shared(sh);
    int tid  = threadIdx.x;
    int lane = tid & 31, wid = tid >> 5;
    int wm = wid >> 2, wn = wid & 3;
    int gID = lane >> 2, qd = lane & 3;
    const int rowBase = blockIdx.y * 128;
    const int colBase = blockIdx.x * 128;
    const int ldc = (MODE == 0) ? KD : Cc;
    const __half* Agm = A + (size_t)rowBase * Kd;
    const __half* Bgm = B + (size_t)colBase * Kd;

    const uint32_t la_off = (uint32_t)(((lane & 15)*HSTRIDE + (lane >> 4)*8) * 2);
    const uint32_t lb_off = (uint32_t)(((lane & 7)*HSTRIDE + ((lane >> 3) & 1)*8) * 2);
    const uint32_t aw_off = (uint32_t)(wm*64*HSTRIDE*2);
    const uint32_t bw_off = (uint32_t)(wn*32*HSTRIDE*2);

    float acc[4][4][4];
    #pragma unroll
    for (int i = 0; i < 4; i++)
        #pragma unroll
        for (int j = 0; j < 4; j++)
            #pragma unroll
            for (int t = 0; t < 4; t++) acc[i][j][t] = 0.f;

    const int nKT = Kd >> 6;

    // prologue: stage 0
    {
        uint32_t stA = shBase;
        uint32_t stB = stA + TEN_BYTES;
        #pragma unroll
        for (int e = 0; e < 4; e++) {
            int idx = tid + e*256;
            int r = idx >> 3, q = idx & 7;
            uint32_t so = (uint32_t)((r*HSTRIDE + q*8) * 2);
            cp_async16(stA + so, Agm + (size_t)r*Kd + q*8);
            cp_async16(stB + so, Bgm + (size_t)r*Kd + q*8);
        }
        CP_COMMIT();
    }

    for (int kt = 0; kt < nKT; kt++) {
        CP_WAIT(0);
        __syncthreads();
        if (kt + 1 < nKT) {
            uint32_t stA = shBase + ((kt+1) & 1)*STG_BYTES;
            uint32_t stB = stA + TEN_BYTES;
            int koff = (kt + 1) * KT;
            #pragma unroll
            for (int e = 0; e < 4; e++) {
                int idx = tid + e*256;
                int r = idx >> 3, q = idx & 7;
                uint32_t so = (uint32_t)((r*HSTRIDE + q*8) * 2);
                cp_async16(stA + so, Agm + (size_t)r*Kd + koff + q*8);
                cp_async16(stB + so, Bgm + (size_t)r*Kd + koff + q*8);
            }
            CP_COMMIT();
        }

        uint32_t aBase = shBase + (kt & 1)*STG_BYTES + aw_off + la_off;
        uint32_t bBase = shBase + (kt & 1)*STG_BYTES + TEN_BYTES + bw_off + lb_off;
        #pragma unroll
        for (int ks = 0; ks < 4; ks++) {
            uint32_t kOff = (uint32_t)(ks * 16 * 2);
            uint32_t bf[4][2];
            #pragma unroll
            for (int j = 0; j < 4; j++)
                ldsm_x2(bf[j][0], bf[j][1], bBase + (uint32_t)(j*8*HSTRIDE*2) + kOff);
            #pragma unroll
            for (int i = 0; i < 4; i++) {
                uint32_t a0, a1, a2, a3;
                ldsm_x4(a0, a1, a2, a3, aBase + (uint32_t)(i*16*HSTRIDE*2) + kOff);
                #pragma unroll
                for (int j = 0; j < 4; j++) {
                    asm volatile(
                        "mma.sync.aligned.m16n8k16.row.col.f32.f16.f16.f32 "
                        "{%0,%1,%2,%3}, {%4,%5,%6,%7}, {%8,%9}, {%0,%1,%2,%3};"
                        : "+f"(acc[i][j][0]), "+f"(acc[i][j][1]),
                          "+f"(acc[i][j][2]), "+f"(acc[i][j][3])
                        : "r"(a0), "r"(a1), "r"(a2), "r"(a3),
                          "r"(bf[j][0]), "r"(bf[j][1]));
                }
            }
        }
        __syncthreads();
    }

    // ---- epilogue ----
    #pragma unroll
    for (int i = 0; i < 4; i++) {
        int r0 = rowBase + wm*64 + i*16 + gID;
        int r1 = r0 + 8;
        float s0 = 1.f, s1 = 1.f;
        if (MODE == 0) {
            s0 = d_rinv[r0];
            s1 = d_rinv[r1];
        } else if (MODE == 2) {
            bool firstHalf = (colBase < Cc/2);
            s0 = (firstHalf ? d_z[r0] : d_z2[r0]) * escale;
            s1 = (firstHalf ? d_z[r1] : d_z2[r1]) * escale;
        }
        unsigned long long best0 = 0ull, best1 = 0ull;
        #pragma unroll
        for (int j = 0; j < 4; j++) {
            int c0 = colBase + wn*32 + j*8 + 2*qd;
            float v00 = acc[i][j][0], v01 = acc[i][j][1];
            float v10 = acc[i][j][2], v11 = acc[i][j][3];
            if (MODE == 1) {
                float b0 = bias[c0], b1 = bias[c0+1];
                v00 += b0; v01 += b1; v10 += b0; v11 += b1;
            } else {
                v00 *= s0; v01 *= s0; v10 *= s1; v11 *= s1;
            }
            *(float2*)(C1 + (size_t)r0*ldc + c0) = make_float2(v00, v01);
            *(float2*)(C1 + (size_t)r1*ldc + c0) = make_float2(v10, v11);
            if (MODE == 0) {
                uint32_t k00 = __float_as_uint(v00); k00 ^= (k00 & 0x80000000u) ? 0xFFFFFFFFu : 0x80000000u;
                uint32_t k01 = __float_as_uint(v01); k01 ^= (k01 & 0x80000000u) ? 0xFFFFFFFFu : 0x80000000u;
                uint32_t k10 = __float_as_uint(v10); k10 ^= (k10 & 0x80000000u) ? 0xFFFFFFFFu : 0x80000000u;
                uint32_t k11 = __float_as_uint(v11); k11 ^= (k11 & 0x80000000u) ? 0xFFFFFFFFu : 0x80000000u;
                unsigned long long p00 = ((unsigned long long)k00 << 32) | (uint32_t)(KD-1-c0);
                unsigned long long p01 = ((unsigned long long)k01 << 32) | (uint32_t)(KD-2-c0);
                unsigned long long p10 = ((unsigned long long)k10 << 32) | (uint32_t)(KD-1-c0);
                unsigned long long p11 = ((unsigned long long)k11 << 32) | (uint32_t)(KD-2-c0);
                if (p01 > p00) p00 = p01;
                if (p11 > p10) p10 = p11;
                if (p00 > best0) best0 = p00;
                if (p10 > best1) best1 = p10;
            }
        }
        if (MODE == 0) {
            #pragma unroll
            for (int o = 1; o <= 2; o <<= 1) {
                unsigned long long t0 = __shfl_xor_sync(0xffffffffu, best0, o);
                unsigned long long t1 = __shfl_xor_sync(0xffffffffu, best1, o);
                if (t0 > best0) best0 = t0;
                if (t1 > best1) best1 = t1;
            }
            if (qd == 0) {
                atomicMax(&d_best[r0], best0);
                atomicMax(&d_best[r1], best1);
            }
        }
    }
}

// ---------------- merged init: norm_units + gw convert + zeroing ------------
__global__ void k_initB(const float* __restrict__ gw, const float* __restrict__ uw) {
    __shared__ float red[256];
    int k = blockIdx.x, ch = threadIdx.x;
    float v = uw[(size_t)k*Cc + ch];
    red[ch] = v*v; __syncthreads();
    for (int o = 128; o; o >>= 1) {
        if (ch < o) red[ch] += red[ch+o];
        __syncthreads();
    }
    float inv = 1.0f / fmaxf(sqrtf(red[0]), EPS_NORM);
    d_bigBh[(size_t)(Cc + k)*Cc + ch] = __float2half(v*inv);

    int g = k*256 + ch;
    if (k < 256) d_bigBh[g] = __float2half(gw[g]);
    if (g < Nn) d_best[g] = 0ull;
    else if (g < Nn + KD) d_cnt[g - Nn] = 0;
    else if (g < Nn + KD + 2*Cc) d_kmean[g - Nn - KD] = 0.f;
}

// fused: x -> xfh + rinv + qcat
__global__ __launch_bounds__(256)
void k_transnorm(const float* __restrict__ x, const float* __restrict__ power) {
    __shared__ float tile[256][33];
    int b  = blockIdx.y;
    int s0 = blockIdx.x * 32;
    int tid = threadIdx.x;
    int tx = tid & 31, ty = tid >> 5;
    for (int c = ty; c < Cc; c += 8)
        tile[c][tx] = x[((size_t)(b*Cc + c))*HW + s0 + tx];
    __syncthreads();
    int lane = tx, wrp = ty;
    float pv[8];
    #pragma unroll
    for (int j = 0; j < 8; j++) pv[j] = sigp(power[lane + j*32]);
    #pragma unroll
    for (int t = 0; t < 4; t++) {
        int p = wrp + t*8;
        float vals[8];
        float ss = 0.f;
        #pragma unroll
        for (int j = 0; j < 8; j++) {
            float v = tile[lane + j*32][p];
            vals[j] = v;
            ss += v*v;
        }
        #pragma unroll
        for (int o = 16; o; o >>= 1) ss += __shfl_xor_sync(0xffffffffu, ss, o);
        float inv = 1.0f / fmaxf(sqrtf(ss), EPS_NORM);
        size_t row = (size_t)b*HW + s0 + p;
        if (lane == 0) d_rinv[row] = inv;
        #pragma unroll
        for (int j = 0; j < 8; j++) {
            int c = lane + j*32;
            float v  = vals[j];
            float vn = v * inv;
            d_xfh[row*Cc + c] = __float2half(v);
            float qp, qn;
            pow_pair(vn, pv[j], qp, qn);
            d_qcat[row*(2*Cc) + c]      = __float2half(qp);
            d_qcat[row*(2*Cc) + Cc + c] = __float2half(qn);
        }
    }
}

// ---------------- counting-sort EMA path -------------------------------------
__device__ __forceinline__ int best_code(unsigned long long b) {
    return KD - 1 - (int)(uint32_t)(b & 0xFFFFFFFFull);
}

__global__ void k_count() {
    int idx = blockIdx.x * 256 + threadIdx.x;
    atomicAdd(&d_cnt[best_code(d_best[idx])], 1);
}

__global__ void k_scan() {
    __shared__ int s[1024];
    int t = threadIdx.x;
    int v = d_cnt[t];
    s[t] = v; __syncthreads();
    for (int o = 1; o < 1024; o <<= 1) {
        int add = (t >= o) ? s[t-o] : 0;
        __syncthreads();
        s[t] += add;
        __syncthreads();
    }
    d_off[t] = s[t] - v;
    d_cur[t] = s[t] - v;
}

__global__ void k_fill() {
    int idx = blockIdx.x * 256 + threadIdx.x;
    int code = best_code(d_best[idx]);
    int pos = atomicAdd(&d_cur[code], 1);
    d_rowlist[pos] = idx;
}

__global__ void k_update_codes(const float* __restrict__ uw, const float* __restrict__ power) {
    __shared__ float red[256];
    int k = blockIdx.x, ch = threadIdx.x;
    int cnt = d_cnt[k], off = d_off[k];
    float sum = 0.f;
    for (int t = 0; t < cnt; t++) {
        int row = d_rowlist[off + t];
        sum += __half2float(d_xfh[(size_t)row*Cc + ch]);
    }
    float em = sum / ((float)cnt + EPS_Z);
    float mv = uw[(size_t)k*Cc + ch]*RATE + em*(1.0f - RATE);
    d_mnew[(size_t)k*Cc + ch] = mv;
    red[ch] = mv*mv; __syncthreads();
    for (int o = 128; o; o >>= 1) {
        if (ch < o) red[ch] += red[ch+o];
        __syncthreads();
    }
    float inv = 1.0f / fmaxf(sqrtf(red[0]), EPS_NORM);
    float mnv = mv*inv;
    float qp, qn;
    pow_pair(mnv, sigp(power[ch]), qp, qn);
    d_kk[(size_t)k*(2*Cc) + ch]      = qp;
    d_kk[(size_t)k*(2*Cc) + Cc + ch] = qn;
}

__global__ void k_kmean() {
    int col = blockIdx.x * 256 + threadIdx.x;
    int r0 = blockIdx.y * 128;
    float s = 0.f;
    for (int r = r0; r < r0 + 128; r++) s += d_kk[(size_t)r*(2*Cc) + col];
    atomicAdd(&d_kmean[col], s * (1.0f / KD));
}

// KV + fused transpose/XOR/fp16
__global__ __launch_bounds__(256)
void k_gemm_kv()
{
    __shared__ float As[16][68];
    __shared__ float Bs[16][68];
    int tid = threadIdx.x;
    int tx = tid & 15, ty = tid >> 4;
    int rowBase = blockIdx.y * 64, colBase = blockIdx.x * 64;
    float acc[4][4] = {};
    for (int k0 = 0; k0 < KD; k0 += 16) {
        #pragma unroll
        for (int e = 0; e < 4; e++) {
            int t = tid + e*256;
            int kk = t >> 6, r = t & 63;
            As[kk][r] = d_kk[(size_t)(k0 + kk)*(2*Cc) + rowBase + r];
        }
        #pragma unroll
        for (int e = 0; e < 4; e++) {
            int t = tid + e*256;
            int kk = t >> 6, c = t & 63;
            Bs[kk][c] = d_mnew[(size_t)(k0 + kk)*Cc + colBase + c];
        }
        __syncthreads();
        #pragma unroll
        for (int kk = 0; kk < 16; kk++) {
            float a[4], bv[4];
            #pragma unroll
            for (int i = 0; i < 4; i++) a[i]  = As[kk][ty*4 + i];
            #pragma unroll
            for (int j = 0; j < 4; j++) bv[j] = Bs[kk][tx*4 + j];
            #pragma unroll
            for (int i = 0; i < 4; i++)
                #pragma unroll
                for (int j = 0; j < 4; j++) acc[i][j] += a[i]*bv[j];
        }
        __syncthreads();
    }
    #pragma unroll
    for (int i = 0; i < 4; i++) {
        int r = rowBase + ty*4 + i;
        #pragma unroll
        for (int j = 0; j < 4; j++) {
            int jc = colBase + tx*4 + j;
            int rdest = (jc < Cc/2) ? r : (r ^ Cc);
            d_BmatTh[(size_t)jc*(2*Cc) + rdest] = __float2half(acc[i][j]);
        }
    }
}

// ---------------- z from fp16 qcat -------------------------------------------
__global__ void k_zrow() {
    int row  = blockIdx.x * 8 + (threadIdx.x >> 5);
    int lane = threadIdx.x & 31;
    const __half2* q = (const __half2*)(d_qcat + (size_t)row * (2*Cc));
    float s1 = 0.f, s2 = 0.f;
    #pragma unroll
    for (int t = 0; t < 8; t++) {
        int c2 = lane + t*32;
        float2 qf = __half22float2(q[c2]);
        int c = 2*c2;
        float k1a = d_kmean[c],       k1b = d_kmean[c+1];
        float k2a = d_kmean[c ^ Cc],  k2b = d_kmean[(c+1) ^ Cc];
        s1 += qf.x*k1a + qf.y*k1b;
        s2 += qf.x*k2a + qf.y*k2b;
    }
    #pragma unroll
    for (int o = 16; o; o >>= 1) {
        s1 += __shfl_xor_sync(0xffffffffu, s1, o);
        s2 += __shfl_xor_sync(0xffffffffu, s2, o);
    }
    if (lane == 0) {
        d_z [row] = 1.0f / (s1 + EPS_Z);
        d_z2[row] = 1.0f / (s2 + EPS_Z);
    }
}

// ---------------- fused depthwise conv + gate + transpose-out ----------------
__global__ void k_convout(const float* __restrict__ wgt, const float* __restrict__ bias,
                          float* __restrict__ out) {
    __shared__ float tile[32][33];
    int b  = blockIdx.z;
    int s0 = blockIdx.x * 32, c0 = blockIdx.y * 32;
    int tx = threadIdx.x, ty = threadIdx.y;
    int ch = c0 + tx;
    float w[9];
    #pragma unroll
    for (int k = 0; k < 9; k++) w[k] = wgt[ch*9 + k];
    float bs = bias[ch];
    #pragma unroll
    for (int pi = ty; pi < 32; pi += 8) {
        int s = s0 + pi;
        int h = s >> 6, wc = s & 63;
        size_t i = (size_t)b*HW + s;
        float center = d_xo[i*Cc + ch];
        float acc = bs;
        #pragma unroll
        for (int kh = 0; kh < 3; kh++) {
            int hh = h + kh - 1;
            if (hh < 0 || hh >= Hh) continue;
            #pragma unroll
            for (int kw = 0; kw < 3; kw++) {
                int ww2 = wc + kw - 1;
                if (ww2 < 0 || ww2 >= Ww) continue;
                acc += w[kh*3 + kw] * d_xo[(i + (kh-1)*Ww + (kw-1))*Cc + ch];
            }
        }
        tile[pi][tx] = (center + acc) * d_g[i*Cc + ch];
    }
    __syncthreads();
    #pragma unroll
    for (int r = ty; r < 32; r += 8)
        out[((size_t)(b*Cc + c0 + r))*HW + s0 + tx] = tile[tx][r];
}

// ---------------- launch -----------------------------------------------------
extern "C" void kernel_launch(void* const* d_in, const int* in_sizes, int n_in,
                              void* d_out, int out_size)
{
    const float* x       = (const float*)d_in[0];
    const float* units_w = (const float*)d_in[1];
    const float* power   = (const float*)d_in[2];
    const float* g_w     = (const float*)d_in[3];
    const float* g_b     = (const float*)d_in[4];
    const float* dwc_w   = (const float*)d_in[5];
    const float* dwc_b   = (const float*)d_in[6];

    float* out   = (float*)d_out;
    float* score = (float*)d_out + OUT_ELEMS;

    void *p_xfh, *p_g, *p_xo, *p_qcat, *p_bigBh, *p_bmatTh;
    cudaGetSymbolAddress(&p_xfh,    d_xfh);
    cudaGetSymbolAddress(&p_g,      d_g);
    cudaGetSymbolAddress(&p_xo,     d_xo);
    cudaGetSymbolAddress(&p_qcat,   d_qcat);
    cudaGetSymbolAddress(&p_bigBh,  d_bigBh);
    cudaGetSymbolAddress(&p_bmatTh, d_BmatTh);

    static cudaStream_t s1 = nullptr;
    static cudaEvent_t evF = nullptr, evI = nullptr, evG = nullptr, evGd = nullptr,
                       evU = nullptr, evZ = nullptr;
    if (!s1) {
        cudaStreamCreateWithFlags(&s1, cudaStreamNonBlocking);
        cudaEventCreateWithFlags(&evF,  cudaEventDisableTiming);
        cudaEventCreateWithFlags(&evI,  cudaEventDisableTiming);
        cudaEventCreateWithFlags(&evG,  cudaEventDisableTiming);
        cudaEventCreateWithFlags(&evGd, cudaEventDisableTiming);
        cudaEventCreateWithFlags(&evU,  cudaEventDisableTiming);
        cudaEventCreateWithFlags(&evZ,  cudaEventDisableTiming);
        cudaFuncSetAttribute(k_mma<0>, cudaFuncAttributeMaxDynamicSharedMemorySize, MMA_SMEM_BYTES);
        cudaFuncSetAttribute(k_mma<1>, cudaFuncAttributeMaxDynamicSharedMemorySize, MMA_SMEM_BYTES);
        cudaFuncSetAttribute(k_mma<2>, cudaFuncAttributeMaxDynamicSharedMemorySize, MMA_SMEM_BYTES);
    }

    // fork: init chain on s1
    cudaEventRecord(evF, 0);
    cudaStreamWaitEvent(s1, evF, 0);
    k_initB<<<KD, 256, 0, s1>>>(g_w, units_w);
    cudaEventRecord(evI, s1);

    k_transnorm<<<dim3(HW/32, Bb), 256>>>(x, power);

    // join init; fork g-GEMM onto s1 (overlaps score GEMM + EMA chain)
    cudaStreamWaitEvent(0, evI, 0);
    cudaEventRecord(evG, 0);
    cudaStreamWaitEvent(s1, evG, 0);
    k_mma<1><<<dim3(Cc/128, Nn/128), 256, MMA_SMEM_BYTES, s1>>>(
        (const __half*)p_xfh, (const __half*)p_bigBh, (float*)p_g, g_b, Cc, 1.f);
    cudaEventRecord(evGd, s1);

    // score = (xf @ mn0^T) * rinv  (fused argmax)
    k_mma<0><<<dim3(KD/128, Nn/128), 256, MMA_SMEM_BYTES>>>(
        (const __half*)p_xfh, (const __half*)p_bigBh + (size_t)Cc*Cc, score, nullptr, Cc, 1.f);

    k_count<<<Nn/256, 256>>>();
    k_scan<<<1, 1024>>>();
    k_fill<<<Nn/256, 256>>>();
    k_update_codes<<<KD, 256>>>(units_w, power);

    // fork: kmean+zrow on s1 parallel with gemm_kv on stream 0
    cudaEventRecord(evU, 0);
    cudaStreamWaitEvent(s1, evU, 0);
    k_kmean<<<dim3(2, 8), 256, 0, s1>>>();
    k_zrow<<<Nn/8, 256, 0, s1>>>();
    cudaEventRecord(evZ, s1);

    k_gemm_kv<<<dim3(Cc/64, (2*Cc)/64), 256>>>();

    // join zrow; xo = qcat @ BmatTh^T * z/N
    cudaStreamWaitEvent(0, evZ, 0);
    k_mma<2><<<dim3(Cc/128, Nn/128), 256, MMA_SMEM_BYTES>>>(
        (const __half*)p_qcat, (const __half*)p_bmatTh, (float*)p_xo, nullptr, 2*Cc, 1.0f/(float)Nn);

    // join g before convout
    cudaStreamWaitEvent(0, evGd, 0);
    dim3 tb(32, 8);
    k_convout<<<dim3(HW/32, Cc/32, Bb), tb>>>(dwc_w, dwc_b, out);
}

// round 17
// speedup vs baseline: 1.2194x; 1.2194x over previous
#include <cuda_runtime.h>
#include <cuda_fp16.h>
#include <cstdint>
#include <math.h>

// Problem constants (fixed shapes for this dataset)
#define Bb   8
#define Cc   256
#define Hh   64
#define Ww   64
#define HW   (Hh*Ww)          // 4096
#define Nn   (Bb*HW)          // 32768
#define KD   1024
#define OUT_ELEMS ((size_t)Bb*Cc*HW)   // 8388608

#define EPS_NORM 1e-12f
#define EPS_Z    1e-6f
#define RATE     0.999f

// ---------------- scratch (device globals; no allocation allowed) -----------
__device__ __half d_xfh [(size_t)Nn*Cc];
__device__ float  d_rinv[Nn];
__device__ float  d_g   [(size_t)Nn*Cc];
__device__ float  d_xo  [(size_t)Nn*Cc];
__device__ __half d_qcat[(size_t)Nn*2*Cc];
__device__ __half d_bigBh[(size_t)(Cc+KD)*Cc];  // rows 0-255: g_w; 256-1279: mn0
__device__ float  d_mnew[(size_t)KD*Cc];
__device__ float  d_kk  [(size_t)KD*2*Cc];
__device__ int    d_cnt [KD];
__device__ int    d_off [KD];
__device__ int    d_cur [KD];
__device__ int    d_rowlist[Nn];
__device__ unsigned long long d_best[Nn];
__device__ float  d_p   [Cc];
__device__ float  d_kmean[2*Cc];
__device__ __half d_BmatTh[(size_t)Cc*2*Cc];  // 256 x 512 (transposed, NO 1/N)
__device__ float  d_z [Nn];
__device__ float  d_z2[Nn];

// ---------------- helpers -----------------------------------------------------
__device__ __forceinline__ void cp_async16(uint32_t smem_dst, const void* gsrc) {
    asm volatile("cp.async.cg.shared.global [%0], [%1], 16;" :: "r"(smem_dst), "l"(gsrc));
}
#define CP_COMMIT() asm volatile("cp.async.commit_group;" ::: "memory")
#define CP_WAIT(n)  asm volatile("cp.async.wait_group %0;" :: "n"(n) : "memory")

__device__ __forceinline__ void ldsm_x4(uint32_t& r0, uint32_t& r1, uint32_t& r2,
                                        uint32_t& r3, uint32_t a) {
    asm volatile("ldmatrix.sync.aligned.m8n8.x4.shared.b16 {%0,%1,%2,%3}, [%4];"
        : "=r"(r0), "=r"(r1), "=r"(r2), "=r"(r3) : "r"(a));
}
__device__ __forceinline__ void ldsm_x2(uint32_t& r0, uint32_t& r1, uint32_t a) {
    asm volatile("ldmatrix.sync.aligned.m8n8.x2.shared.b16 {%0,%1}, [%2];"
        : "=r"(r0), "=r"(r1) : "r"(a));
}

// pow(|v|, p) with sign split: one LG2 + one EX2 for both branches
__device__ __forceinline__ void pow_pair(float v, float p, float& qp, float& qn) {
    float e = exp2f(p * __log2f(fabsf(v)));   // v==0 -> log2=-inf -> e=0
    qp = (v > 0.f) ? e : 0.f;
    qn = (v < 0.f) ? e : 0.f;
}

// ---------------- fp16 mma.sync NT GEMM (3-stage cp.async, KT=64, ldmatrix) --
// MODE 3: merged g+score — C1=d_g (+bias, cols<256), C2=score (*rinv, fused argmax)
// MODE 2: xo — C1=xo, scale by (col<128 ? z : z2) * escale
#define KT       64
#define HSTRIDE  72                          // 64 + 8 pad (144B rows: ldsm conflict-free)
#define TEN_HALVES (128*HSTRIDE)             // one tensor (A or B) per stage
#define STG_HALVES (2*TEN_HALVES)
#define STG_BYTES  (STG_HALVES*2)            // 36864
#define TEN_BYTES  (TEN_HALVES*2)
#define MMA_SMEM_BYTES (3*STG_BYTES)         // 110592

template<int MODE>
__global__ __launch_bounds__(256)
void k_mma(const __half* __restrict__ A, const __half* __restrict__ B,
           float* __restrict__ C1, float* __restrict__ C2,
           const float* __restrict__ bias, int Kd, float escale)
{
    extern __shared__ __half sh[];
    const uint32_t shBase = (uint32_t)__cvta_generic_to_shared(sh);
    int tid  = threadIdx.x;
    int lane = tid & 31, wid = tid >> 5;
    int wm = wid >> 2, wn = wid & 3;       // 2 x 4 warp grid
    int gID = lane >> 2, qd = lane & 3;
    const int rowBase = blockIdx.y * 128;
    const int colBase = blockIdx.x * 128;
    const __half* Agm = A + (size_t)rowBase * Kd;
    const __half* Bgm = B + (size_t)colBase * Kd;

    const uint32_t la_off = (uint32_t)(((lane & 15)*HSTRIDE + (lane >> 4)*8) * 2);
    const uint32_t lb_off = (uint32_t)(((lane & 7)*HSTRIDE + ((lane >> 3) & 1)*8) * 2);
    const uint32_t aw_off = (uint32_t)(wm*64*HSTRIDE*2);
    const uint32_t bw_off = (uint32_t)(wn*32*HSTRIDE*2);

    float acc[4][4][4];
    #pragma unroll
    for (int i = 0; i < 4; i++)
        #pragma unroll
        for (int j = 0; j < 4; j++)
            #pragma unroll
            for (int t = 0; t < 4; t++) acc[i][j][t] = 0.f;

    const int nKT = Kd >> 6;   // KT = 64

    // prologue: stages 0,1
    #pragma unroll
    for (int s = 0; s < 2; s++) {
        uint32_t stA = shBase + s*STG_BYTES;
        uint32_t stB = stA + TEN_BYTES;
        int koff = s * KT;
        #pragma unroll
        for (int e = 0; e < 4; e++) {
            int idx = tid + e*256;
            int r = idx >> 3, q = idx & 7;
            uint32_t so = (uint32_t)((r*HSTRIDE + q*8) * 2);
            cp_async16(stA + so, Agm + (size_t)r*Kd + koff + q*8);
            cp_async16(stB + so, Bgm + (size_t)r*Kd + koff + q*8);
        }
        CP_COMMIT();
    }

    int stCur = 0, stPre = 2;
    for (int kt = 0; kt < nKT; kt++) {
        if (kt < nKT - 1) { CP_WAIT(1); } else { CP_WAIT(0); }
        __syncthreads();
        if (kt + 2 < nKT) {
            uint32_t stA = shBase + stPre*STG_BYTES;
            uint32_t stB = stA + TEN_BYTES;
            int koff = (kt + 2) * KT;
            #pragma unroll
            for (int e = 0; e < 4; e++) {
                int idx = tid + e*256;
                int r = idx >> 3, q = idx & 7;
                uint32_t so = (uint32_t)((r*HSTRIDE + q*8) * 2);
                cp_async16(stA + so, Agm + (size_t)r*Kd + koff + q*8);
                cp_async16(stB + so, Bgm + (size_t)r*Kd + koff + q*8);
            }
            CP_COMMIT();
        }

        uint32_t aBase = shBase + stCur*STG_BYTES + aw_off + la_off;
        uint32_t bBase = shBase + stCur*STG_BYTES + TEN_BYTES + bw_off + lb_off;
        #pragma unroll
        for (int ks = 0; ks < 4; ks++) {
            uint32_t kOff = (uint32_t)(ks * 16 * 2);
            uint32_t bf[4][2];
            uint32_t af[4][4];
            #pragma unroll
            for (int j = 0; j < 4; j++)
                ldsm_x2(bf[j][0], bf[j][1], bBase + (uint32_t)(j*8*HSTRIDE*2) + kOff);
            #pragma unroll
            for (int i = 0; i < 4; i++)
                ldsm_x4(af[i][0], af[i][1], af[i][2], af[i][3],
                        aBase + (uint32_t)(i*16*HSTRIDE*2) + kOff);
            #pragma unroll
            for (int i = 0; i < 4; i++) {
                #pragma unroll
                for (int j = 0; j < 4; j++) {
                    asm volatile(
                        "mma.sync.aligned.m16n8k16.row.col.f32.f16.f16.f32 "
                        "{%0,%1,%2,%3}, {%4,%5,%6,%7}, {%8,%9}, {%0,%1,%2,%3};"
                        : "+f"(acc[i][j][0]), "+f"(acc[i][j][1]),
                          "+f"(acc[i][j][2]), "+f"(acc[i][j][3])
                        : "r"(af[i][0]), "r"(af[i][1]), "r"(af[i][2]), "r"(af[i][3]),
                          "r"(bf[j][0]), "r"(bf[j][1]));
                }
            }
        }
        stCur++; if (stCur == 3) stCur = 0;
        stPre++; if (stPre == 3) stPre = 0;
    }

    // ---- epilogue ----
    bool scoreTile = (MODE == 3) && (colBase >= Cc);
    #pragma unroll
    for (int i = 0; i < 4; i++) {
        int r0 = rowBase + wm*64 + i*16 + gID;
        int r1 = r0 + 8;
        float s0 = 1.f, s1 = 1.f;
        if (MODE == 2) {
            bool firstHalf = (colBase < Cc/2);
            s0 = (firstHalf ? d_z[r0] : d_z2[r0]) * escale;
            s1 = (firstHalf ? d_z[r1] : d_z2[r1]) * escale;
        } else if (scoreTile) {
            s0 = d_rinv[r0];
            s1 = d_rinv[r1];
        }
        unsigned long long best0 = 0ull, best1 = 0ull;
        #pragma unroll
        for (int j = 0; j < 4; j++) {
            int c0 = colBase + wn*32 + j*8 + 2*qd;
            float v00 = acc[i][j][0], v01 = acc[i][j][1];
            float v10 = acc[i][j][2], v11 = acc[i][j][3];
            if (MODE == 2) {
                v00 *= s0; v01 *= s0; v10 *= s1; v11 *= s1;
                *(float2*)(C1 + (size_t)r0*Cc + c0) = make_float2(v00, v01);
                *(float2*)(C1 + (size_t)r1*Cc + c0) = make_float2(v10, v11);
            } else if (!scoreTile) {
                float b0 = bias[c0], b1 = bias[c0+1];
                v00 += b0; v01 += b1; v10 += b0; v11 += b1;
                *(float2*)(C1 + (size_t)r0*Cc + c0) = make_float2(v00, v01);
                *(float2*)(C1 + (size_t)r1*Cc + c0) = make_float2(v10, v11);
            } else {
                int cs = c0 - Cc;
                v00 *= s0; v01 *= s0; v10 *= s1; v11 *= s1;
                *(float2*)(C2 + (size_t)r0*KD + cs) = make_float2(v00, v01);
                *(float2*)(C2 + (size_t)r1*KD + cs) = make_float2(v10, v11);
                uint32_t k00 = __float_as_uint(v00); k00 ^= (k00 & 0x80000000u) ? 0xFFFFFFFFu : 0x80000000u;
                uint32_t k01 = __float_as_uint(v01); k01 ^= (k01 & 0x80000000u) ? 0xFFFFFFFFu : 0x80000000u;
                uint32_t k10 = __float_as_uint(v10); k10 ^= (k10 & 0x80000000u) ? 0xFFFFFFFFu : 0x80000000u;
                uint32_t k11 = __float_as_uint(v11); k11 ^= (k11 & 0x80000000u) ? 0xFFFFFFFFu : 0x80000000u;
                unsigned long long p00 = ((unsigned long long)k00 << 32) | (uint32_t)(KD-1-cs);
                unsigned long long p01 = ((unsigned long long)k01 << 32) | (uint32_t)(KD-2-cs);
                unsigned long long p10 = ((unsigned long long)k10 << 32) | (uint32_t)(KD-1-cs);
                unsigned long long p11 = ((unsigned long long)k11 << 32) | (uint32_t)(KD-2-cs);
                if (p01 > p00) p00 = p01;
                if (p11 > p10) p10 = p11;
                if (p00 > best0) best0 = p00;
                if (p10 > best1) best1 = p10;
            }
        }
        if (scoreTile) {
            #pragma unroll
            for (int o = 1; o <= 2; o <<= 1) {
                unsigned long long t0 = __shfl_xor_sync(0xffffffffu, best0, o);
                unsigned long long t1 = __shfl_xor_sync(0xffffffffu, best1, o);
                if (t0 > best0) best0 = t0;
                if (t1 > best1) best1 = t1;
            }
            if (qd == 0) {
                atomicMax(&d_best[r0], best0);
                atomicMax(&d_best[r1], best1);
            }
        }
    }
}

// ---------------- merged init: gw convert into bigB + p + zero best/cnt/kmean
__global__ void k_init(const float* __restrict__ power, const float* __restrict__ gw) {
    int idx = blockIdx.x * 256 + threadIdx.x;      // 65536 threads
    d_bigBh[idx] = __float2half(gw[idx]);          // rows 0-255 of bigB
    if (idx < Nn) d_best[idx] = 0ull;
    if (idx < KD) d_cnt[idx] = 0;
    if (idx < 2*Cc) d_kmean[idx] = 0.f;
    if (idx < Cc) {
        float pw = power[idx];
        d_p[idx] = 1.0f + 4.0f / (1.0f + __expf(-pw));
    }
}

// one block per codebook row -> normalized fp16 into bigB rows 256..1279
__global__ void k_norm_units(const float* __restrict__ uw) {
    __shared__ float red[256];
    int k = blockIdx.x, ch = threadIdx.x;
    float v = uw[(size_t)k*Cc + ch];
    red[ch] = v*v; __syncthreads();
    for (int o = 128; o; o >>= 1) {
        if (ch < o) red[ch] += red[ch+o];
        __syncthreads();
    }
    float inv = 1.0f / fmaxf(sqrtf(red[0]), EPS_NORM);
    d_bigBh[(size_t)(Cc + k)*Cc + ch] = __float2half(v*inv);
}

// fused: x (B,C,HW) -> xfh (fp16) + rinv + power features qcat (fp16)
__global__ __launch_bounds__(256)
void k_transnorm(const float* __restrict__ x) {
    __shared__ float tile[256][33];
    int b  = blockIdx.y;
    int s0 = blockIdx.x * 32;
    int tid = threadIdx.x;
    int tx = tid & 31, ty = tid >> 5;
    for (int c = ty; c < Cc; c += 8)
        tile[c][tx] = x[((size_t)(b*Cc + c))*HW + s0 + tx];
    __syncthreads();
    int lane = tx, wrp = ty;
    #pragma unroll
    for (int t = 0; t < 4; t++) {
        int p = wrp + t*8;
        float vals[8];
        float ss = 0.f;
        #pragma unroll
        for (int j = 0; j < 8; j++) {
            float v = tile[lane + j*32][p];
            vals[j] = v;
            ss += v*v;
        }
        #pragma unroll
        for (int o = 16; o; o >>= 1) ss += __shfl_xor_sync(0xffffffffu, ss, o);
        float inv = 1.0f / fmaxf(sqrtf(ss), EPS_NORM);
        size_t row = (size_t)b*HW + s0 + p;
        if (lane == 0) d_rinv[row] = inv;
        #pragma unroll
        for (int j = 0; j < 8; j++) {
            int c = lane + j*32;
            float v  = vals[j];
            float vn = v * inv;
            d_xfh[row*Cc + c] = __float2half(v);
            float qp, qn;
            pow_pair(vn, d_p[c], qp, qn);
            d_qcat[row*(2*Cc) + c]      = __float2half(qp);
            d_qcat[row*(2*Cc) + Cc + c] = __float2half(qn);
        }
    }
}

// ---------------- counting-sort EMA path -------------------------------------
__device__ __forceinline__ int best_code(unsigned long long b) {
    return KD - 1 - (int)(uint32_t)(b & 0xFFFFFFFFull);
}

__global__ void k_count() {
    int idx = blockIdx.x * 256 + threadIdx.x;
    atomicAdd(&d_cnt[best_code(d_best[idx])], 1);
}

__global__ void k_scan() {   // 1 block, 1024 threads: exclusive scan
    __shared__ int s[1024];
    int t = threadIdx.x;
    int v = d_cnt[t];
    s[t] = v; __syncthreads();
    for (int o = 1; o < 1024; o <<= 1) {
        int add = (t >= o) ? s[t-o] : 0;
        __syncthreads();
        s[t] += add;
        __syncthreads();
    }
    d_off[t] = s[t] - v;
    d_cur[t] = s[t] - v;
}

__global__ void k_fill() {
    int idx = blockIdx.x * 256 + threadIdx.x;
    int code = best_code(d_best[idx]);
    int pos = atomicAdd(&d_cur[code], 1);
    d_rowlist[pos] = idx;
}

__global__ void k_update_codes(const float* __restrict__ uw) {
    __shared__ float red[256];
    int k = blockIdx.x, ch = threadIdx.x;
    int cnt = d_cnt[k], off = d_off[k];
    float sum = 0.f;
    for (int t = 0; t < cnt; t++) {
        int row = d_rowlist[off + t];
        sum += __half2float(d_xfh[(size_t)row*Cc + ch]);
    }
    float em = sum / ((float)cnt + EPS_Z);
    float mv = uw[(size_t)k*Cc + ch]*RATE + em*(1.0f - RATE);
    d_mnew[(size_t)k*Cc + ch] = mv;
    red[ch] = mv*mv; __syncthreads();
    for (int o = 128; o; o >>= 1) {
        if (ch < o) red[ch] += red[ch+o];
        __syncthreads();
    }
    float inv = 1.0f / fmaxf(sqrtf(red[0]), EPS_NORM);
    float mnv = mv*inv;
    float qp, qn;
    pow_pair(mnv, d_p[ch], qp, qn);
    d_kk[(size_t)k*(2*Cc) + ch]      = qp;
    d_kk[(size_t)k*(2*Cc) + Cc + ch] = qn;
}

__global__ void k_kmean() {  // grid (2, 8), 256 threads
    int col = blockIdx.x * 256 + threadIdx.x;
    int r0 = blockIdx.y * 128;
    float s = 0.f;
    for (int r = r0; r < r0 + 128; r++) s += d_kk[(size_t)r*(2*Cc) + col];
    atomicAdd(&d_kmean[col], s * (1.0f / KD));
}

// KV + fused transpose/XOR/fp16: BmatTh[j][rdest] = kvfull[r][j]
__global__ __launch_bounds__(256)
void k_gemm_kv()
{
    __shared__ float As[16][68];
    __shared__ float Bs[16][68];
    int tid = threadIdx.x;
    int tx = tid & 15, ty = tid >> 4;
    int rowBase = blockIdx.y * 64, colBase = blockIdx.x * 64;
    float acc[4][4] = {};
    for (int k0 = 0; k0 < KD; k0 += 16) {
        #pragma unroll
        for (int e = 0; e < 4; e++) {
            int t = tid + e*256;
            int kk = t >> 6, r = t & 63;
            As[kk][r] = d_kk[(size_t)(k0 + kk)*(2*Cc) + rowBase + r];
        }
        #pragma unroll
        for (int e = 0; e < 4; e++) {
            int t = tid + e*256;
            int kk = t >> 6, c = t & 63;
            Bs[kk][c] = d_mnew[(size_t)(k0 + kk)*Cc + colBase + c];
        }
        __syncthreads();
        #pragma unroll
        for (int kk = 0; kk < 16; kk++) {
            float a[4], bv[4];
            #pragma unroll
            for (int i = 0; i < 4; i++) a[i]  = As[kk][ty*4 + i];
            #pragma unroll
            for (int j = 0; j < 4; j++) bv[j] = Bs[kk][tx*4 + j];
            #pragma unroll
            for (int i = 0; i < 4; i++)
                #pragma unroll
                for (int j = 0; j < 4; j++) acc[i][j] += a[i]*bv[j];
        }
        __syncthreads();
    }
    #pragma unroll
    for (int i = 0; i < 4; i++) {
        int r = rowBase + ty*4 + i;
        #pragma unroll
        for (int j = 0; j < 4; j++) {
            int jc = colBase + tx*4 + j;
            int rdest = (jc < Cc/2) ? r : (r ^ Cc);
            d_BmatTh[(size_t)jc*(2*Cc) + rdest] = __float2half(acc[i][j]);
        }
    }
}

// ---------------- z from fp16 qcat (one warp per row) -------------------------
__global__ void k_zrow() {
    int row  = blockIdx.x * 8 + (threadIdx.x >> 5);
    int lane = threadIdx.x & 31;
    const __half2* q = (const __half2*)(d_qcat + (size_t)row * (2*Cc));
    float s1 = 0.f, s2 = 0.f;
    #pragma unroll
    for (int t = 0; t < 8; t++) {
        int c2 = lane + t*32;
        float2 qf = __half22float2(q[c2]);
        int c = 2*c2;
        float k1a = d_kmean[c],       k1b = d_kmean[c+1];
        float k2a = d_kmean[c ^ Cc],  k2b = d_kmean[(c+1) ^ Cc];
        s1 += qf.x*k1a + qf.y*k1b;
        s2 += qf.x*k2a + qf.y*k2b;
    }
    #pragma unroll
    for (int o = 16; o; o >>= 1) {
        s1 += __shfl_xor_sync(0xffffffffu, s1, o);
        s2 += __shfl_xor_sync(0xffffffffu, s2, o);
    }
    if (lane == 0) {
        d_z [row] = 1.0f / (s1 + EPS_Z);
        d_z2[row] = 1.0f / (s2 + EPS_Z);
    }
}

// ---------------- fused depthwise conv + gate + transpose-out ----------------
__global__ void k_convout(const float* __restrict__ wgt, const float* __restrict__ bias,
                          float* __restrict__ out) {
    __shared__ float tile[32][33];
    int b  = blockIdx.z;
    int s0 = blockIdx.x * 32, c0 = blockIdx.y * 32;
    int tx = threadIdx.x, ty = threadIdx.y;
    int ch = c0 + tx;
    float w[9];
    #pragma unroll
    for (int k = 0; k < 9; k++) w[k] = wgt[ch*9 + k];
    float bs = bias[ch];
    #pragma unroll
    for (int pi = ty; pi < 32; pi += 8) {
        int s = s0 + pi;
        int h = s >> 6, wc = s & 63;
        size_t i = (size_t)b*HW + s;
        float center = d_xo[i*Cc + ch];
        float acc = bs;
        #pragma unroll
        for (int kh = 0; kh < 3; kh++) {
            int hh = h + kh - 1;
            if (hh < 0 || hh >= Hh) continue;
            #pragma unroll
            for (int kw = 0; kw < 3; kw++) {
                int ww2 = wc + kw - 1;
                if (ww2 < 0 || ww2 >= Ww) continue;
                acc += w[kh*3 + kw] * d_xo[(i + (kh-1)*Ww + (kw-1))*Cc + ch];
            }
        }
        tile[pi][tx] = (center + acc) * d_g[i*Cc + ch];
    }
    __syncthreads();
    #pragma unroll
    for (int r = ty; r < 32; r += 8)
        out[((size_t)(b*Cc + c0 + r))*HW + s0 + tx] = tile[tx][r];
}

// ---------------- launch -----------------------------------------------------
extern "C" void kernel_launch(void* const* d_in, const int* in_sizes, int n_in,
                              void* d_out, int out_size)
{
    const float* x       = (const float*)d_in[0];
    const float* units_w = (const float*)d_in[1];
    const float* power   = (const float*)d_in[2];
    const float* g_w     = (const float*)d_in[3];
    const float* g_b     = (const float*)d_in[4];
    const float* dwc_w   = (const float*)d_in[5];
    const float* dwc_b   = (const float*)d_in[6];

    float* out   = (float*)d_out;                  // (B,C,H,W)
    float* score = (float*)d_out + OUT_ELEMS;      // (N, K)

    void *p_xfh, *p_g, *p_xo, *p_qcat, *p_bigBh, *p_bmatTh;
    cudaGetSymbolAddress(&p_xfh,    d_xfh);
    cudaGetSymbolAddress(&p_g,      d_g);
    cudaGetSymbolAddress(&p_xo,     d_xo);
    cudaGetSymbolAddress(&p_qcat,   d_qcat);
    cudaGetSymbolAddress(&p_bigBh,  d_bigBh);
    cudaGetSymbolAddress(&p_bmatTh, d_BmatTh);

    static cudaStream_t s1 = nullptr;
    static cudaEvent_t evU = nullptr, evZ = nullptr;
    if (!s1) {
        cudaStreamCreateWithFlags(&s1, cudaStreamNonBlocking);
        cudaEventCreateWithFlags(&evU, cudaEventDisableTiming);
        cudaEventCreateWithFlags(&evZ, cudaEventDisableTiming);
        cudaFuncSetAttribute(k_mma<3>, cudaFuncAttributeMaxDynamicSharedMemorySize, MMA_SMEM_BYTES);
        cudaFuncSetAttribute(k_mma<2>, cudaFuncAttributeMaxDynamicSharedMemorySize, MMA_SMEM_BYTES);
    }

    k_init<<<(Cc*Cc)/256, 256>>>(power, g_w);
    k_norm_units<<<KD, 256>>>(units_w);
    k_transnorm<<<dim3(HW/32, Bb), 256>>>(x);

    // merged: [g | score] = xfh @ bigB^T  (fp16 mma, fused bias / rinv+argmax)
    k_mma<3><<<dim3((Cc+KD)/128, Nn/128), 256, MMA_SMEM_BYTES>>>(
        (const __half*)p_xfh, (const __half*)p_bigBh, (float*)p_g, score, g_b, Cc, 1.f);

    k_count<<<Nn/256, 256>>>();
    k_scan<<<1, 1024>>>();
    k_fill<<<Nn/256, 256>>>();
    k_update_codes<<<KD, 256>>>(units_w);

    // fork: kmean+zrow on s1 overlapped with gemm_kv on stream 0
    cudaEventRecord(evU, 0);
    cudaStreamWaitEvent(s1, evU, 0);
    k_kmean<<<dim3(2, 8), 256, 0, s1>>>();
    k_zrow<<<Nn/8, 256, 0, s1>>>();
    cudaEventRecord(evZ, s1);

    k_gemm_kv<<<dim3(Cc/64, (2*Cc)/64), 256>>>();

    // join zrow; xo = qcat @ BmatTh^T * z/N   (fp16 mma)
    cudaStreamWaitEvent(0, evZ, 0);
    k_mma<2><<<dim3(Cc/128, Nn/128), 256, MMA_SMEM_BYTES>>>(
        (const __half*)p_qcat, (const __half*)p_bmatTh, (float*)p_xo, nullptr, nullptr, 2*Cc, 1.0f/(float)Nn);

    dim3 tb(32, 8);
    k_convout<<<dim3(HW/32, Cc/32, Bb), tb>>>(dwc_w, dwc_b, out);
}